// round 3
// baseline (speedup 1.0000x reference)
#include <cuda_runtime.h>

#define NQ     1224
#define TWOQ   2448
#define SMAX   50
#define SM1    (SMAX - 1)
#define BATCHN 1024
#define ROWS   (BATCHN * SM1)          // 50176
#define VEC4   (TWOQ / 4)              // 612 float4 per batch row
#define WARPS_PER_BLOCK 8
#define THREADS 256
#define BLOCKS  784
#define TOTAL_WARPS (BLOCKS * WARPS_PER_BLOCK)   // 6272
#define ROWS_PER_WARP (ROWS / TOTAL_WARPS)       // 8 exactly
#define FULLM 0xffffffffu

__device__ float g_buckets[TOTAL_WARPS];

__device__ __forceinline__ unsigned nz4(const float4& v) {
    return __float_as_uint(v.x) | __float_as_uint(v.y) |
           __float_as_uint(v.z) | __float_as_uint(v.w);
}

__device__ __forceinline__ int locate4(const float4& v, int i) {
    int base = i * 4;
    if (v.x != 0.0f) return base;
    if (v.y != 0.0f) return base + 1;
    if (v.z != 0.0f) return base + 2;
    return base + 3;
}

struct Scan {
    const float4* rp;     // current batch row (float4 base), warp-uniform
    const float*  pp;     // pred row base for (b, t-1), warp-uniform
    int   c;              // chunk cursor (float4 units), warp-uniform
    int   nextRow;        // warp-uniform
    int   rowsLeft;       // warp-uniform
    bool  active;         // warp-uniform
    // pending gather (lane 0 only)
    float pendP;
    bool  pendValid;
    bool  pendCorr;
};

__device__ __forceinline__ void start_row(Scan& s,
                                          const float* __restrict__ batch,
                                          const float* __restrict__ pred) {
    const int row = s.nextRow++;
    s.rowsLeft--;
    const int b = row / SM1;
    const int t = row - b * SM1 + 1;               // 1..49
    s.rp = (const float4*)(batch + ((size_t)b * SMAX + t) * TWOQ);
    s.pp = pred + ((size_t)b * SMAX + (t - 1)) * NQ;
    s.c  = 0;
}

// Row finished (loc = per-lane one-hot position, or -1). Consume the pending
// gather from the PREVIOUS row (its LDG has had a full row-scan to complete),
// issue this row's gather, advance the stream.
__device__ __forceinline__ void finish_row(Scan& s, int loc, int lane,
                                           float& acc,
                                           const float* __restrict__ batch,
                                           const float* __restrict__ pred) {
    const int j = __reduce_max_sync(FULLM, loc);
    if (lane == 0) {
        if (s.pendValid && s.pendP > 0.0f) {
            const float x = s.pendCorr ? s.pendP : (1.0f - s.pendP);
            acc -= logf(x);
        }
        if (j >= 0) {
            const int q = (j < NQ) ? j : (j - NQ);
            s.pendP     = __ldg(s.pp + q);     // deferred: consumed next finish
            s.pendCorr  = (j < NQ);
            s.pendValid = true;
        } else {
            s.pendValid = false;
        }
    }
    if (s.rowsLeft > 0) start_row(s, batch, pred);
    else                s.active = false;
}

__global__ __launch_bounds__(THREADS)
void loss_kernel(const float* __restrict__ pred,
                 const float* __restrict__ batch) {
    const int wid  = threadIdx.x >> 5;
    const int lane = threadIdx.x & 31;
    const int gw   = blockIdx.x * WARPS_PER_BLOCK + wid;   // 0..6271

    float acc = 0.0f;                       // meaningful on lane 0

    Scan A, B;
    A.pendValid = false; B.pendValid = false;
    // stream A: rows [gw*8, gw*8+4), stream B: rows [gw*8+4, gw*8+8)
    A.nextRow = gw * ROWS_PER_WARP;
    A.rowsLeft = ROWS_PER_WARP / 2;
    B.nextRow = gw * ROWS_PER_WARP + ROWS_PER_WARP / 2;
    B.rowsLeft = ROWS_PER_WARP / 2;
    A.active = true; B.active = true;
    start_row(A, batch, pred);
    start_row(B, batch, pred);

    const float4 z = make_float4(0.f, 0.f, 0.f, 0.f);

    #pragma unroll 1
    while (A.active | B.active) {
        unsigned na = 0, nb = 0;
        float4 a0 = z, a1 = z, b0 = z, b1 = z;
        int ia0 = 0, ib0 = 0;

        if (A.active) {
            ia0 = A.c + lane;                 // < 612 always (max 607)
            const int ia1 = ia0 + 32;
            a0 = A.rp[ia0];
            a1 = (ia1 < VEC4) ? A.rp[ia1] : z;
            na = nz4(a0) | nz4(a1);
        }
        if (B.active) {
            ib0 = B.c + lane;
            const int ib1 = ib0 + 32;
            b0 = B.rp[ib0];
            b1 = (ib1 < VEC4) ? B.rp[ib1] : z;
            nb = nz4(b0) | nz4(b1);
        }

        bool fA = false, fB = false;
        if (__ballot_sync(FULLM, (na | nb) != 0)) {
            const unsigned wa = __ballot_sync(FULLM, na != 0);
            const unsigned wb = __ballot_sync(FULLM, nb != 0);
            fA = A.active && (wa != 0);
            fB = B.active && (wb != 0);
            if (fA) {
                int loc = -1;
                if (na) loc = nz4(a0) ? locate4(a0, ia0) : locate4(a1, ia0 + 32);
                finish_row(A, loc, lane, acc, batch, pred);
            }
            if (fB) {
                int loc = -1;
                if (nb) loc = nz4(b0) ? locate4(b0, ib0) : locate4(b1, ib0 + 32);
                finish_row(B, loc, lane, acc, batch, pred);
            }
        }
        if (A.active && !fA) {
            A.c += 64;
            if (A.c >= VEC4) finish_row(A, -1, lane, acc, batch, pred);
        }
        if (B.active && !fB) {
            B.c += 64;
            if (B.c >= VEC4) finish_row(B, -1, lane, acc, batch, pred);
        }
    }

    // flush remaining pendings and publish this warp's partial sum
    if (lane == 0) {
        if (A.pendValid && A.pendP > 0.0f)
            acc -= logf(A.pendCorr ? A.pendP : (1.0f - A.pendP));
        if (B.pendValid && B.pendP > 0.0f)
            acc -= logf(B.pendCorr ? B.pendP : (1.0f - B.pendP));
        g_buckets[gw] = acc;
    }
}

__global__ __launch_bounds__(1024)
void reduce_kernel(float* __restrict__ out) {
    __shared__ float sh[1024];
    float s = 0.0f;
    for (int i = threadIdx.x; i < TOTAL_WARPS; i += 1024)
        s += g_buckets[i];
    sh[threadIdx.x] = s;
    __syncthreads();
    #pragma unroll
    for (int off = 512; off > 0; off >>= 1) {
        if (threadIdx.x < off) sh[threadIdx.x] += sh[threadIdx.x + off];
        __syncthreads();
    }
    if (threadIdx.x == 0) out[0] = sh[0];
}

extern "C" void kernel_launch(void* const* d_in, const int* in_sizes, int n_in,
                              void* d_out, int out_size) {
    const float* pred  = (const float*)d_in[0];
    const float* batch = (const float*)d_in[1];
    float* out = (float*)d_out;

    loss_kernel<<<BLOCKS, THREADS>>>(pred, batch);
    reduce_kernel<<<1, 1024>>>(out);
}

// round 4
// speedup vs baseline: 1.2303x; 1.2303x over previous
#include <cuda_runtime.h>

#define NQ     1224
#define TWOQ   2448
#define SMAX   50
#define SM1    (SMAX - 1)
#define ROWS   (1024 * SM1)            // 50176
#define VEC4   (TWOQ / 4)              // 612 float4 per batch row
#define WPB    8
#define THREADS 256
#define BLOCKS (ROWS / (WPB * 2))      // 3136 (2 rows per warp)
#define FULLM  0xffffffffu

__global__ void init_out_kernel(float* out) {
    if (threadIdx.x == 0) out[0] = 0.0f;
}

__device__ __forceinline__ unsigned nz4(const float4& v) {
    return __float_as_uint(v.x) | __float_as_uint(v.y) |
           __float_as_uint(v.z) | __float_as_uint(v.w);
}

__device__ __forceinline__ int locate4(const float4& v, int i) {
    int base = i * 4;
    if (v.x != 0.0f) return base;
    if (v.y != 0.0f) return base + 1;
    if (v.z != 0.0f) return base + 2;
    return base + 3;
}

// loc within the (v0 @ i0, v1 @ i0+32) pair; caller guarantees pair nonzero
__device__ __forceinline__ int locate_pair(const float4& v0, const float4& v1,
                                           int i0) {
    return nz4(v0) ? locate4(v0, i0) : locate4(v1, i0 + 32);
}

__global__ __launch_bounds__(THREADS)
void loss_kernel(const float* __restrict__ pred,
                 const float* __restrict__ batch,
                 float* __restrict__ out) {
    __shared__ float warp_part[WPB];

    const int wid  = threadIdx.x >> 5;
    const int lane = threadIdx.x & 31;
    const int gw   = blockIdx.x * WPB + wid;       // 0..25087

    const int rowA = gw * 2;
    const int rowB = rowA + 1;

    const int bA = rowA / SM1, tA = rowA - bA * SM1 + 1;   // 1..49
    const int bB = rowB / SM1, tB = rowB - bB * SM1 + 1;

    const float4* __restrict__ rpA =
        (const float4*)(batch + ((size_t)bA * SMAX + tA) * TWOQ);
    const float4* __restrict__ rpB =
        (const float4*)(batch + ((size_t)bB * SMAX + tB) * TWOQ);
    const float* __restrict__ ppA = pred + ((size_t)bA * SMAX + (tA - 1)) * NQ;
    const float* __restrict__ ppB = pred + ((size_t)bB * SMAX + (tB - 1)) * NQ;

    const float4 z = make_float4(0.f, 0.f, 0.f, 0.f);

    int jA = -1, jB = -1;
    int c = 0;

    // Phase 1: scan both rows together. 4 LDG.128 per lane per iter
    // (2 KB/warp in flight), ONE ballot on the common path.
    #pragma unroll 1
    for (; c < VEC4; c += 64) {
        const int i0 = c + lane;            // < 612 always
        const int i1 = i0 + 32;
        const bool g = (i1 < VEC4);
        float4 a0 = rpA[i0];
        float4 b0 = rpB[i0];
        float4 a1 = g ? rpA[i1] : z;
        float4 b1 = g ? rpB[i1] : z;

        const unsigned na = nz4(a0) | nz4(a1);
        const unsigned nb = nz4(b0) | nz4(b1);

        if (__ballot_sync(FULLM, na | nb)) {
            const unsigned wa = __ballot_sync(FULLM, na != 0);
            const unsigned wb = __ballot_sync(FULLM, nb != 0);
            if (wa) {
                const int loc = na ? locate_pair(a0, a1, i0) : -1;
                jA = __reduce_max_sync(FULLM, loc);
            }
            if (wb) {
                const int loc = nb ? locate_pair(b0, b1, i0) : -1;
                jB = __reduce_max_sync(FULLM, loc);
            }
            c += 64;
            break;
        }
    }

    // Phase 2: finish whichever stream is still unresolved (at most one
    // in practice; both loops kept for robustness).
    if (jA < 0) {
        #pragma unroll 1
        for (int cc = c; cc < VEC4; cc += 64) {
            const int i0 = cc + lane;
            const int i1 = i0 + 32;
            float4 a0 = rpA[i0];
            float4 a1 = (i1 < VEC4) ? rpA[i1] : z;
            const unsigned na = nz4(a0) | nz4(a1);
            if (__ballot_sync(FULLM, na)) {
                const int loc = na ? locate_pair(a0, a1, i0) : -1;
                jA = __reduce_max_sync(FULLM, loc);
                break;
            }
        }
    }
    if (jB < 0) {
        #pragma unroll 1
        for (int cc = c; cc < VEC4; cc += 64) {
            const int i0 = cc + lane;
            const int i1 = i0 + 32;
            float4 b0 = rpB[i0];
            float4 b1 = (i1 < VEC4) ? rpB[i1] : z;
            const unsigned nb = nz4(b0) | nz4(b1);
            if (__ballot_sync(FULLM, nb)) {
                const int loc = nb ? locate_pair(b0, b1, i0) : -1;
                jB = __reduce_max_sync(FULLM, loc);
                break;
            }
        }
    }

    // Epilogue (lane 0): issue both pred gathers back-to-back, then logs.
    float contrib = 0.0f;
    if (lane == 0) {
        float pA = 1.0f, pB = 1.0f;
        bool  vA = false, vB = false;
        if (jA >= 0) {
            const int q = (jA < NQ) ? jA : (jA - NQ);
            pA = __ldg(ppA + q);
            vA = true;
        }
        if (jB >= 0) {
            const int q = (jB < NQ) ? jB : (jB - NQ);
            pB = __ldg(ppB + q);
            vB = true;
        }
        if (vA && pA > 0.0f) contrib -= __logf((jA < NQ) ? pA : (1.0f - pA));
        if (vB && pB > 0.0f) contrib -= __logf((jB < NQ) ? pB : (1.0f - pB));
        warp_part[wid] = contrib;
    }
    __syncthreads();

    if (threadIdx.x == 0) {
        float s = 0.0f;
        #pragma unroll
        for (int w = 0; w < WPB; ++w) s += warp_part[w];
        atomicAdd(out, s);
    }
}

extern "C" void kernel_launch(void* const* d_in, const int* in_sizes, int n_in,
                              void* d_out, int out_size) {
    const float* pred  = (const float*)d_in[0];
    const float* batch = (const float*)d_in[1];
    float* out = (float*)d_out;

    init_out_kernel<<<1, 32>>>(out);
    loss_kernel<<<BLOCKS, THREADS>>>(pred, batch, out);
}